// round 6
// baseline (speedup 1.0000x reference)
#include <cuda_runtime.h>
#include <cuda_bf16.h>
#include <string.h>
#include <math.h>

// ---------------- problem constants ----------------
#define EID   30000
#define EMB   256
#define HID   512
#define SRC_T 128
#define TRG_T 50
#define B     64
#define G3    1536
#define NB_ENC 192
#define NB_DEC 296
#define KF    832          // padded [x(257); zeros(63); h(512)] length
#define LT    938          // logits tiles of 32 cols (938*32 = 30016 >= 30000)

// ---------------- device state ----------------
__device__ float g_hT[2 * HID * B];                  // transposed hidden [k][b], double buffered
__device__ float g_giEnc[(size_t)SRC_T * B * G3];    // encoder gi (incl b_ih)
__device__ float g_A[8 * B * G3];                    // gh partials
__device__ float g_Bp[5 * B * G3];                   // gi partials (decoder)
__device__ float g_C[12 * B * HID];                  // r1 partials
__device__ float g_logits[B * EID];
__device__ float g_xfull[KF * B];                    // transposed padded decoder input
__device__ float g_xcat[(EMB + HID) * B];            // transposed concat(emb_mt, h)
__device__ float g_rate[B];
__device__ int   g_idx[B];
__device__ float g_pm[B * 5], g_ps[B * 5];
__device__ int   g_pi[B * 5];
__device__ float g_lse[B];
__device__ unsigned g_cnt, g_gen, g_ticket;

// ---------------- packed fp32 FMA ----------------
__device__ __forceinline__ float2 ffma2(float2 a, float2 b, float2 c) {
    unsigned long long ua, ub, uc, ud;
    memcpy(&ua, &a, 8); memcpy(&ub, &b, 8); memcpy(&uc, &c, 8);
    asm("fma.rn.f32x2 %0, %1, %2, %3;" : "=l"(ud) : "l"(ua), "l"(ub), "l"(uc));
    float2 d; memcpy(&d, &ud, 8); return d;
}

// ---------------- grid barrier (sense via generation counter) ----------------
__device__ __forceinline__ void gbar(unsigned nb) {
    __syncthreads();
    if (threadIdx.x == 0) {
        __threadfence();
        unsigned g = *(volatile unsigned*)&g_gen;
        if (atomicAdd(&g_cnt, 1u) == nb - 1u) {
            g_cnt = 0u;
            __threadfence();
            *(volatile unsigned*)&g_gen = g + 1u;
        } else {
            while (*(volatile unsigned*)&g_gen == g) { __nanosleep(64); }
        }
        __threadfence();
    }
    __syncthreads();
}

// ---------------- shared 4x4 float2 GEMM tile (64 cols x 64 k) ----------------
__device__ __forceinline__ void mm64_4x4(const float* __restrict__ xs,
                                         const float* __restrict__ ws,
                                         int bpg, int cg, float2 acc[4][4]) {
    #pragma unroll 4
    for (int k = 0; k < 64; k++) {
        float2 xv[4];
        #pragma unroll
        for (int i = 0; i < 4; i++)
            xv[i] = *reinterpret_cast<const float2*>(&xs[k * 66 + 2 * (bpg + 8 * i)]);
        #pragma unroll
        for (int c = 0; c < 4; c++) {
            float w = ws[(cg * 4 + c) * 65 + k];
            float2 wp = make_float2(w, w);
            #pragma unroll
            for (int i = 0; i < 4; i++) acc[i][c] = ffma2(xv[i], wp, acc[i][c]);
        }
    }
}

__device__ __forceinline__ void store_4x4(float* __restrict__ dst, int N, int n0,
                                          int bpg, int cg, float2 acc[4][4]) {
    #pragma unroll
    for (int c = 0; c < 4; c++) {
        int n = n0 + cg * 4 + c;
        #pragma unroll
        for (int i = 0; i < 4; i++) {
            int p = bpg + 8 * i;
            dst[(size_t)(2 * p) * N + n]     = acc[i][c].x;
            dst[(size_t)(2 * p + 1) * N + n] = acc[i][c].y;
        }
    }
}

// ---------------- small prep kernels ----------------
__global__ void init_state(const int* __restrict__ trg_eid, const float* __restrict__ trg_rate) {
    int i = blockIdx.x * 256 + threadIdx.x;
    if (i < HID * B) g_hT[i] = 0.f;
    if (i < B) { g_idx[i] = trg_eid[i]; g_rate[i] = trg_rate[i]; }
}

__global__ void enc_gi(const float* __restrict__ src, const float* __restrict__ W_ih,
                       const float* __restrict__ b_ih) {
    int j = blockIdx.x * 256 + threadIdx.x;
    int tb = blockIdx.y;
    if (j < G3) {
        const float* x = src + (size_t)tb * 3;
        g_giEnc[(size_t)tb * G3 + j] = b_ih[j] + x[0] * W_ih[j * 3] + x[1] * W_ih[j * 3 + 1]
                                              + x[2] * W_ih[j * 3 + 2];
    }
}

// ---------------- encoder: all 128 masked GRU steps, one kernel ----------------
__global__ __launch_bounds__(128, 2)
void encoder_all(const float* __restrict__ W_hh, const float* __restrict__ b_hh,
                 const int* __restrict__ src_len) {
    __shared__ __align__(16) float xs[64 * 66];
    __shared__ __align__(16) float ws[64 * 65];
    const int bx = blockIdx.x, tid = threadIdx.x;
    const int jn = bx % 24, jk = bx / 24;
    const int n0 = jn * 64, k0 = jk * 64;
    const int bpg = tid & 7, cg = tid >> 3;

    // persist W tile across all 128 steps
    for (int e = tid; e < 4096; e += 128) {
        int nl = e >> 6, k = e & 63;
        ws[nl * 65 + k] = W_hh[(size_t)(n0 + nl) * HID + k0 + k];
    }

    for (int t = 0; t < SRC_T; t++) {
        const float* h = g_hT + (t & 1) * HID * B;
        float* hn = g_hT + ((t + 1) & 1) * HID * B;
        __syncthreads();
        for (int e = tid; e < 4096; e += 128) {
            int k = e >> 6, b = e & 63;
            xs[k * 66 + b] = h[(k0 + k) * 64 + b];
        }
        __syncthreads();
        float2 acc[4][4];
        #pragma unroll
        for (int i = 0; i < 4; i++)
            #pragma unroll
            for (int c = 0; c < 4; c++) acc[i][c] = make_float2(0.f, 0.f);
        mm64_4x4(xs, ws, bpg, cg, acc);
        store_4x4(g_A + (size_t)jk * B * G3, G3, n0, bpg, cg, acc);
        gbar(NB_ENC);
        // combine
        for (int i = bx * 128 + tid; i < B * HID; i += NB_ENC * 128) {
            int b = i >> 9, j = i & 511;
            float ar = b_hh[j], az = b_hh[j + 512], an = b_hh[j + 1024];
            #pragma unroll
            for (int p = 0; p < 8; p++) {
                const float* ba = g_A + ((size_t)p * B + b) * G3;
                ar += ba[j]; az += ba[j + 512]; an += ba[j + 1024];
            }
            const float* gi = g_giEnc + ((size_t)t * B + b) * G3;
            float r = 1.f / (1.f + expf(-(ar + gi[j])));
            float z = 1.f / (1.f + expf(-(az + gi[j + 512])));
            float n = tanhf(gi[j + 1024] + r * an);
            float ho = h[j * 64 + b];
            float hv = (1.f - z) * n + z * ho;
            if (!(t < src_len[b])) hv = ho;
            hn[j * 64 + b] = hv;
        }
        gbar(NB_ENC);
    }
}

// ---------------- decoder: all 49 steps, one persistent mega-kernel ----------------
__global__ __launch_bounds__(128, 2)
void decoder_mega(const float* __restrict__ emb_dec,
                  const float* __restrict__ W_ih, const float* __restrict__ W_hh,
                  const float* __restrict__ b_ih, const float* __restrict__ b_hh,
                  const float* __restrict__ emb_mt,
                  const float* __restrict__ W_eid, const float* __restrict__ b_eid,
                  const float* __restrict__ W_r1, const float* __restrict__ b_r1,
                  const float* __restrict__ W_r2, const float* __restrict__ b_r2,
                  float* __restrict__ out) {
    __shared__ __align__(16) float xs[64 * 66];
    __shared__ __align__(16) float ws[64 * 65];
    __shared__ unsigned sh_t;
    const int bx = blockIdx.x, tid = threadIdx.x;
    const int bpg = tid & 7,  cg  = tid >> 3;   // 4x4 tiling
    const int bpgL = tid & 15, cgL = tid >> 4;  // logits 2x4 tiling
    float* out_rate = out + (size_t)TRG_T * B * EID;
    int hb = 0;

    for (int s = 0; s < TRG_T - 1; s++) {
        const float* hcur = g_hT + hb * HID * B;
        float* hnew = g_hT + (hb ^ 1) * HID * B;

        // P1: build padded xfull; reset logits ticket
        for (int i = bx * 128 + tid; i < KF * B; i += NB_DEC * 128) {
            int k = i >> 6, b = i & 63; float v;
            if (k < EMB)       v = emb_dec[(size_t)g_idx[b] * EMB + k];
            else if (k == EMB) v = g_rate[b];
            else if (k < 320)  v = 0.f;
            else               v = hcur[(k - 320) * 64 + b];
            g_xfull[i] = v;
        }
        if (bx == 0 && tid == 0) g_ticket = 0u;
        gbar(NB_DEC);

        // P2: gi + gh GEMM partials over padded K (jobs: 24 n-tiles x 13 k-chunks)
        for (int job = bx; job < 312; job += NB_DEC) {
            int jn = job % 24, jk = job / 24;
            int n0 = jn * 64, k0 = jk * 64;
            __syncthreads();
            for (int e = tid; e < 4096; e += 128) {
                int nl = e >> 6, k = e & 63, kk = k0 + k; float w;
                if (jk < 5) w = (kk < EMB + 1) ? W_ih[(size_t)(n0 + nl) * (EMB + 1) + kk] : 0.f;
                else        w = W_hh[(size_t)(n0 + nl) * HID + (kk - 320)];
                ws[nl * 65 + k] = w;
            }
            for (int e = tid; e < 4096; e += 128) {
                int k = e >> 6, b = e & 63;
                xs[k * 66 + b] = g_xfull[(k0 + k) * 64 + b];
            }
            __syncthreads();
            float2 acc[4][4];
            #pragma unroll
            for (int i = 0; i < 4; i++)
                #pragma unroll
                for (int c = 0; c < 4; c++) acc[i][c] = make_float2(0.f, 0.f);
            mm64_4x4(xs, ws, bpg, cg, acc);
            float* dst = (jk < 5) ? (g_Bp + (size_t)jk * B * G3) : (g_A + (size_t)(jk - 5) * B * G3);
            store_4x4(dst, G3, n0, bpg, cg, acc);
        }
        gbar(NB_DEC);

        // P3: GRU combine
        for (int i = bx * 128 + tid; i < B * HID; i += NB_DEC * 128) {
            int b = i >> 9, j = i & 511;
            float ar = b_hh[j], az = b_hh[j + 512], an = b_hh[j + 1024];
            #pragma unroll
            for (int p = 0; p < 8; p++) {
                const float* ba = g_A + ((size_t)p * B + b) * G3;
                ar += ba[j]; az += ba[j + 512]; an += ba[j + 1024];
            }
            float br = b_ih[j], bz = b_ih[j + 512], bn = b_ih[j + 1024];
            #pragma unroll
            for (int p = 0; p < 5; p++) {
                const float* bb = g_Bp + ((size_t)p * B + b) * G3;
                br += bb[j]; bz += bb[j + 512]; bn += bb[j + 1024];
            }
            float r = 1.f / (1.f + expf(-(ar + br)));
            float z = 1.f / (1.f + expf(-(az + bz)));
            float n = tanhf(bn + r * an);
            float ho = hcur[j * 64 + b];
            hnew[j * 64 + b] = (1.f - z) * n + z * ho;
        }
        gbar(NB_DEC);

        // P4: logits GEMM [64,512]x[512,30000], ticket-scheduled 32-col tiles
        for (;;) {
            __syncthreads();
            if (tid == 0) sh_t = atomicAdd(&g_ticket, 1u);
            __syncthreads();
            unsigned t = sh_t;
            if (t >= LT) break;
            int n0 = (int)t * 32;
            float2 acc[2][4];
            #pragma unroll
            for (int i = 0; i < 2; i++)
                #pragma unroll
                for (int c = 0; c < 4; c++) acc[i][c] = make_float2(0.f, 0.f);
            for (int kt = 0; kt < HID; kt += 64) {
                __syncthreads();
                for (int e = tid; e < 4096; e += 128) {
                    int k = e >> 6, b = e & 63;
                    xs[k * 66 + b] = hnew[(kt + k) * 64 + b];
                }
                for (int e = tid; e < 2048; e += 128) {
                    int nl = e >> 6, k = e & 63, n = n0 + nl;
                    ws[nl * 65 + k] = (n < EID) ? W_eid[(size_t)n * HID + kt + k] : 0.f;
                }
                __syncthreads();
                #pragma unroll 4
                for (int k = 0; k < 64; k++) {
                    float2 x0 = *reinterpret_cast<const float2*>(&xs[k * 66 + 2 * bpgL]);
                    float2 x1 = *reinterpret_cast<const float2*>(&xs[k * 66 + 2 * (bpgL + 16)]);
                    #pragma unroll
                    for (int c = 0; c < 4; c++) {
                        float w = ws[(cgL * 4 + c) * 65 + k];
                        float2 wp = make_float2(w, w);
                        acc[0][c] = ffma2(x0, wp, acc[0][c]);
                        acc[1][c] = ffma2(x1, wp, acc[1][c]);
                    }
                }
            }
            #pragma unroll
            for (int c = 0; c < 4; c++) {
                int n = n0 + cgL * 4 + c;
                if (n >= EID) continue;
                float bv = b_eid[n];
                g_logits[(size_t)(2 * bpgL) * EID + n]            = acc[0][c].x + bv;
                g_logits[(size_t)(2 * bpgL + 1) * EID + n]        = acc[0][c].y + bv;
                g_logits[(size_t)(2 * (bpgL + 16)) * EID + n]     = acc[1][c].x + bv;
                g_logits[(size_t)(2 * (bpgL + 16) + 1) * EID + n] = acc[1][c].y + bv;
            }
        }
        gbar(NB_DEC);

        // P5: online-softmax partials: 320 jobs = 64 batches x 5 slices of 6000
        for (int job = bx; job < 320; job += NB_DEC) {
            int b = job % 64, sl = job / 64;
            const float* L = g_logits + (size_t)b * EID;
            int nb0 = sl * 6000, nb1 = nb0 + 6000;
            float m = -3.4e38f, sum = 0.f; int ix = 0x7fffffff;
            for (int n = nb0 + tid; n < nb1; n += 128) {
                float v = L[n];
                if (v > m) { sum = sum * expf(m - v) + 1.f; m = v; ix = n; }
                else       sum += expf(v - m);
            }
            float* rm = xs; float* rs = xs + 128; int* ri = (int*)(xs + 256);
            __syncthreads();
            rm[tid] = m; rs[tid] = sum; ri[tid] = ix;
            __syncthreads();
            for (int st = 64; st; st >>= 1) {
                if (tid < st) {
                    float m1 = rm[tid], m2 = rm[tid + st];
                    float s1 = rs[tid], s2 = rs[tid + st];
                    int i1 = ri[tid], i2 = ri[tid + st];
                    float M = fmaxf(m1, m2);
                    rs[tid] = s1 * expf(m1 - M) + s2 * expf(m2 - M);
                    rm[tid] = M;
                    ri[tid] = (m2 > m1) ? i2 : ((m1 > m2) ? i1 : min(i1, i2));
                }
                __syncthreads();
            }
            if (tid == 0) { g_pm[b * 5 + sl] = rm[0]; g_ps[b * 5 + sl] = rs[0]; g_pi[b * 5 + sl] = ri[0]; }
            __syncthreads();
        }
        gbar(NB_DEC);

        // P6: finalize lse + first-index argmax
        if (bx < 64 && tid == 0) {
            float M = -3.4e38f, S = 0.f; int I = 0x7fffffff;
            for (int sl = 0; sl < 5; sl++) {
                float m2 = g_pm[bx * 5 + sl], s2 = g_ps[bx * 5 + sl];
                int i2 = g_pi[bx * 5 + sl];
                float Mn = fmaxf(M, m2);
                S = S * expf(M - Mn) + s2 * expf(m2 - Mn);
                I = (m2 > M) ? i2 : ((M > m2) ? I : min(I, i2));
                M = Mn;
            }
            g_lse[bx] = M + logf(S);
            g_idx[bx] = I;
        }
        gbar(NB_DEC);

        // P7: write normalized logits to out; build xcat
        for (int job = bx; job < 320; job += NB_DEC) {
            int b = job % 64, sl = job / 64;
            float lse = g_lse[b];
            const float* L = g_logits + (size_t)b * EID;
            float* O = out + ((size_t)(s + 1) * B + b) * EID;
            for (int n = sl * 6000 + tid; n < sl * 6000 + 6000; n += 128) O[n] = L[n] - lse;
        }
        for (int i = bx * 128 + tid; i < (EMB + HID) * B; i += NB_DEC * 128) {
            int k = i >> 6, b = i & 63;
            g_xcat[i] = (k < EMB) ? emb_mt[(size_t)g_idx[b] * EMB + k] : hnew[(k - EMB) * 64 + b];
        }
        gbar(NB_DEC);

        // P8: r1 GEMM partials: 96 jobs on blocks 0..95 (8 n-tiles x 12 k-chunks)
        if (bx < 96) {
            int jn = bx & 7, jk = bx >> 3;
            int n0 = jn * 64, k0 = jk * 64;
            __syncthreads();
            for (int e = tid; e < 4096; e += 128) {
                int nl = e >> 6, k = e & 63;
                ws[nl * 65 + k] = W_r1[(size_t)(n0 + nl) * (EMB + HID) + k0 + k];
            }
            for (int e = tid; e < 4096; e += 128) {
                int k = e >> 6, b = e & 63;
                xs[k * 66 + b] = g_xcat[(k0 + k) * 64 + b];
            }
            __syncthreads();
            float2 acc[4][4];
            #pragma unroll
            for (int i = 0; i < 4; i++)
                #pragma unroll
                for (int c = 0; c < 4; c++) acc[i][c] = make_float2(0.f, 0.f);
            mm64_4x4(xs, ws, bpg, cg, acc);
            store_4x4(g_C + (size_t)jk * B * HID, HID, n0, bpg, cg, acc);
        }
        gbar(NB_DEC);

        // P9: rate head (blocks 0..63, one batch each)
        if (bx < 64) {
            int b = bx;
            float a = 0.f;
            #pragma unroll
            for (int q = 0; q < 4; q++) {
                int j = tid + 128 * q;
                float v = b_r1[j];
                #pragma unroll
                for (int p = 0; p < 12; p++) v += g_C[((size_t)p * B + b) * HID + j];
                a += fmaxf(v, 0.f) * W_r2[j];
            }
            float* rs = xs;
            __syncthreads();
            rs[tid] = a; __syncthreads();
            for (int st = 64; st; st >>= 1) { if (tid < st) rs[tid] += rs[tid + st]; __syncthreads(); }
            if (tid == 0) {
                float pr = 1.f / (1.f + expf(-(rs[0] + b_r2[0])));
                out_rate[(size_t)(s + 1) * B + b] = pr;
                g_rate[b] = pr;
            }
        }
        gbar(NB_DEC);

        hb ^= 1;
    }
}

// ---------------- host launcher ----------------
extern "C" void kernel_launch(void* const* d_in, const int* in_sizes, int n_in,
                              void* d_out, int out_size)
{
    const float* src      = (const float*)d_in[0];
    const int*   src_len  = (const int*)  d_in[1];
    const int*   trg_eid  = (const int*)  d_in[2];
    const float* trg_rate = (const float*)d_in[3];
    const float* W_ih_enc = (const float*)d_in[4];
    const float* W_hh_enc = (const float*)d_in[5];
    const float* b_ih_enc = (const float*)d_in[6];
    const float* b_hh_enc = (const float*)d_in[7];
    const float* emb_dec  = (const float*)d_in[8];
    const float* W_ih_dec = (const float*)d_in[9];
    const float* W_hh_dec = (const float*)d_in[10];
    const float* b_ih_dec = (const float*)d_in[11];
    const float* b_hh_dec = (const float*)d_in[12];
    const float* emb_mt   = (const float*)d_in[13];
    const float* W_eid    = (const float*)d_in[14];
    const float* b_eid    = (const float*)d_in[15];
    const float* W_r1     = (const float*)d_in[16];
    const float* b_r1     = (const float*)d_in[17];
    const float* W_r2     = (const float*)d_in[18];
    const float* b_r2     = (const float*)d_in[19];
    float* out = (float*)d_out;
    float* out_rate = out + (size_t)TRG_T * B * EID;

    // zero output row 0 (eid + rate)
    cudaMemsetAsync(out, 0, (size_t)B * EID * sizeof(float), 0);
    cudaMemsetAsync(out_rate, 0, B * sizeof(float), 0);

    init_state<<<128, 256>>>(trg_eid, trg_rate);
    enc_gi<<<dim3(6, SRC_T * B), 256>>>(src, W_ih_enc, b_ih_enc);
    encoder_all<<<NB_ENC, 128>>>(W_hh_enc, b_hh_enc, src_len);
    decoder_mega<<<NB_DEC, 128>>>(emb_dec, W_ih_dec, W_hh_dec, b_ih_dec, b_hh_dec,
                                  emb_mt, W_eid, b_eid, W_r1, b_r1, W_r2, b_r2, out);
}

// round 8
// speedup vs baseline: 1.1596x; 1.1596x over previous
#include <cuda_runtime.h>
#include <cuda_bf16.h>
#include <string.h>
#include <math.h>

// ---------------- problem constants ----------------
#define EID   30000
#define EMB   256
#define HID   512
#define SRC_T 128
#define TRG_T 50
#define B     64
#define G3    1536
#define KF    832            // merged decoder K: [emb(256); rate(1); pad(63); h(512)]
#define NTILES 477           // 469 logits tiles (64 cols) + 8 Yh tiles

// ---------------- device state ----------------
__device__ float g_hT[2 * HID * B];                   // transposed hidden [k][b], double buffered
__device__ float g_giEnc[(size_t)SRC_T * B * G3];     // encoder gi (incl b_ih)
__device__ float g_Wdec[(size_t)G3 * KF];             // merged decoder GRU weights
__device__ float g_embT[(size_t)EMB * EID];           // emb_mt transposed
__device__ float g_mtProj[(size_t)EID * HID];         // W_r1[:, :256] @ emb_mt[v]
__device__ float g_logits[(size_t)B * EID];
__device__ float g_Yh[B * HID];                       // W_r1[:, 256:768] @ h
__device__ float g_rate[B];
__device__ int   g_idx[B];
__device__ unsigned g_tk[64];                         // per-step ticket counters

// ---------------- packed fp32 FMA ----------------
__device__ __forceinline__ float2 ffma2(float2 a, float2 b, float2 c) {
    unsigned long long ua, ub, uc, ud;
    memcpy(&ua, &a, 8); memcpy(&ub, &b, 8); memcpy(&uc, &c, 8);
    asm("fma.rn.f32x2 %0, %1, %2, %3;" : "=l"(ud) : "l"(ua), "l"(ub), "l"(uc));
    float2 d; memcpy(&d, &ud, 8); return d;
}

__device__ __forceinline__ float sigf(float x) { return 1.f / (1.f + expf(-x)); }

// ---------------- 64x64 GEMM micro-tile (4 pairs x 4 cols per thread, 128 thr) ----------------
__device__ __forceinline__ void mm64_4x4(const float* __restrict__ xs,
                                         const float* __restrict__ ws,
                                         int bpg, int cg, float2 acc[4][4]) {
    #pragma unroll 4
    for (int k = 0; k < 64; k++) {
        float2 xv[4];
        #pragma unroll
        for (int i = 0; i < 4; i++)
            xv[i] = *reinterpret_cast<const float2*>(&xs[k * 66 + 2 * (bpg + 8 * i)]);
        #pragma unroll
        for (int c = 0; c < 4; c++) {
            float w = ws[(cg * 4 + c) * 65 + k];
            float2 wp = make_float2(w, w);
            #pragma unroll
            for (int i = 0; i < 4; i++) acc[i][c] = ffma2(xv[i], wp, acc[i][c]);
        }
    }
}

// GRU inner: 1 x-pair LDS.64 + 1 LDS.128 (3 gate weights) + 3 ffma2 per k
__device__ __forceinline__ void gru_inner(const float* __restrict__ xs,
                                          const float* __restrict__ wp, int kw, int lane,
                                          float2& aR, float2& aZ, float2& aN) {
    #pragma unroll 4
    for (int k = 0; k < kw; k++) {
        float2 x = *reinterpret_cast<const float2*>(&xs[k * 66 + 2 * lane]);
        float4 w = *reinterpret_cast<const float4*>(&wp[(size_t)k * 4]);
        aR = ffma2(x, make_float2(w.x, w.x), aR);
        aZ = ffma2(x, make_float2(w.y, w.y), aZ);
        aN = ffma2(x, make_float2(w.z, w.z), aN);
    }
}

// ---------------- one-time prep kernels ----------------
__global__ void init_state(const int* __restrict__ trg_eid, const float* __restrict__ trg_rate) {
    int i = blockIdx.x * 256 + threadIdx.x;
    if (i < HID * B) g_hT[i] = 0.f;
    if (i < B) { g_idx[i] = trg_eid[i]; g_rate[i] = trg_rate[i]; }
    if (i < 64) g_tk[i] = 0u;
}

__global__ void build_wdec(const float* __restrict__ W_ih, const float* __restrict__ W_hh) {
    int i = blockIdx.x * 256 + threadIdx.x;
    if (i >= G3 * KF) return;
    int j3 = i / KF, k = i - j3 * KF;
    float v = 0.f;
    if (k < EMB + 1)   v = W_ih[(size_t)j3 * (EMB + 1) + k];
    else if (k >= 320) v = W_hh[(size_t)j3 * HID + (k - 320)];
    g_Wdec[i] = v;
}

__global__ void transpose_emb(const float* __restrict__ emb_mt) {
    __shared__ float sm[32][33];
    int v0 = blockIdx.x * 32, k0 = blockIdx.y * 32;
    int tx = threadIdx.x & 31, ty = threadIdx.x >> 5;   // 256 threads: ty 0..7
    #pragma unroll
    for (int i = 0; i < 32; i += 8) {
        int v = v0 + ty + i;
        sm[ty + i][tx] = (v < EID) ? emb_mt[(size_t)v * EMB + k0 + tx] : 0.f;
    }
    __syncthreads();
    #pragma unroll
    for (int i = 0; i < 32; i += 8) {
        int v = v0 + tx;
        if (v < EID) g_embT[(size_t)(k0 + ty + i) * EID + v] = sm[tx][ty + i];
    }
}

// g_mtProj[v][j] = sum_{k<256} emb_mt[v][k] * W_r1[j][k]
__global__ void mtproj_kernel(const float* __restrict__ W_r1) {
    __shared__ float xs[64 * 66];
    __shared__ float ws[64 * 65];
    int tid = threadIdx.x;
    int vt = blockIdx.x % 469, jt = blockIdx.x / 469;
    int v0 = vt * 64, j0 = jt * 64;
    int bpg = tid & 7, cg = tid >> 3;
    float2 acc[4][4];
    #pragma unroll
    for (int i = 0; i < 4; i++)
        #pragma unroll
        for (int c = 0; c < 4; c++) acc[i][c] = make_float2(0.f, 0.f);
    for (int kt = 0; kt < 256; kt += 64) {
        __syncthreads();
        for (int e = tid; e < 4096; e += 128) {
            int k = e >> 6, vl = e & 63; int v = v0 + vl;
            xs[k * 66 + vl] = (v < EID) ? g_embT[(size_t)(kt + k) * EID + v] : 0.f;
        }
        for (int e = tid; e < 4096; e += 128) {
            int nl = e >> 6, k = e & 63;
            ws[nl * 65 + k] = W_r1[(size_t)(j0 + nl) * 768 + kt + k];
        }
        __syncthreads();
        mm64_4x4(xs, ws, bpg, cg, acc);
    }
    #pragma unroll
    for (int c = 0; c < 4; c++) {
        int j = j0 + cg * 4 + c;
        #pragma unroll
        for (int i = 0; i < 4; i++) {
            int v = v0 + 2 * (bpg + 8 * i);
            if (v < EID)     g_mtProj[(size_t)v * HID + j]       = acc[i][c].x;
            if (v + 1 < EID) g_mtProj[(size_t)(v + 1) * HID + j] = acc[i][c].y;
        }
    }
}

__global__ void enc_gi(const float* __restrict__ src, const float* __restrict__ W_ih,
                       const float* __restrict__ b_ih) {
    int j = blockIdx.x * 256 + threadIdx.x;
    int tb = blockIdx.y;
    if (j < G3) {
        const float* x = src + (size_t)tb * 3;
        g_giEnc[(size_t)tb * G3 + j] = b_ih[j] + x[0] * W_ih[j * 3] + x[1] * W_ih[j * 3 + 1]
                                               + x[2] * W_ih[j * 3 + 2];
    }
}

// ---------------- fused encoder GRU step (1 node / step) ----------------
// 128 blocks x 128 thr. Block owns 4 j-values, all 3 gates, full K=512.
__global__ void enc_step_kernel(const float* __restrict__ hin, float* __restrict__ hout,
                                const float* __restrict__ W_hh, const float* __restrict__ b_hh,
                                const float* __restrict__ gi_t, const int* __restrict__ src_len,
                                int t) {
    extern __shared__ float sm[];
    float* ws4 = sm;                 // [4 j][512 k][4 gates]
    float* xs  = sm + 4 * 512 * 4;   // [128 k][66]
    const int tid = threadIdx.x, bx = blockIdx.x;
    const int j0 = bx * 4, jl = tid >> 5, lane = tid & 31;

    for (int e = tid; e < 4 * 512; e += 128) {
        int jj = e >> 9, k = e & 511;
        float* w4 = &ws4[(size_t)(jj * 512 + k) * 4];
        w4[0] = W_hh[(size_t)(j0 + jj) * HID + k];
        w4[1] = W_hh[(size_t)(512 + j0 + jj) * HID + k];
        w4[2] = W_hh[(size_t)(1024 + j0 + jj) * HID + k];
    }

    float2 aR = make_float2(0.f, 0.f), aZ = aR, aN = aR;
    for (int c = 0; c < 4; c++) {
        __syncthreads();
        for (int e = tid; e < 128 * 32; e += 128) {
            int k = e >> 5, bp = e & 31;
            *reinterpret_cast<float2*>(&xs[k * 66 + 2 * bp]) =
                *reinterpret_cast<const float2*>(&hin[(c * 128 + k) * 64 + 2 * bp]);
        }
        __syncthreads();
        gru_inner(xs, ws4 + (size_t)(jl * 512 + c * 128) * 4, 128, lane, aR, aZ, aN);
    }

    int j = j0 + jl;
    float bhr = b_hh[j], bhz = b_hh[j + 512], bhn = b_hh[j + 1024];
    #pragma unroll
    for (int u = 0; u < 2; u++) {
        int b = 2 * lane + u;
        float ghr = u ? aR.y : aR.x, ghz = u ? aZ.y : aZ.x, ghn = u ? aN.y : aN.x;
        const float* gi = gi_t + (size_t)b * G3;
        float r = sigf(gi[j] + ghr + bhr);
        float z = sigf(gi[j + 512] + ghz + bhz);
        float n = tanhf(gi[j + 1024] + r * (ghn + bhn));
        float ho = hin[j * 64 + b];
        float hv = (t < src_len[b]) ? (1.f - z) * n + z * ho : ho;
        hout[j * 64 + b] = hv;
    }
}

// ---------------- fused decoder GRU cell (1 node / step) ----------------
__global__ void dec_gru_kernel(const float* __restrict__ hin, float* __restrict__ hout,
                               const float* __restrict__ emb_dec,
                               const float* __restrict__ b_ih, const float* __restrict__ b_hh) {
    extern __shared__ float sm[];
    float* ws4 = sm;                 // [4 j][832 k][4]
    float* xs  = sm + 4 * KF * 4;    // [128 k][66]
    const int tid = threadIdx.x, bx = blockIdx.x;
    const int j0 = bx * 4, jl = tid >> 5, lane = tid & 31;

    for (int e = tid; e < 4 * KF; e += 128) {
        int jj = e / KF, k = e - jj * KF;
        float* w4 = &ws4[(size_t)(jj * KF + k) * 4];
        w4[0] = g_Wdec[(size_t)(j0 + jj) * KF + k];
        w4[1] = g_Wdec[(size_t)(512 + j0 + jj) * KF + k];
        w4[2] = g_Wdec[(size_t)(1024 + j0 + jj) * KF + k];
    }

    const int koff[7] = {0, 128, 256, 320, 448, 576, 704};
    float2 aR = make_float2(0.f, 0.f), aZ = aR, aNi = aR, aNh = aR;

    for (int c = 0; c < 7; c++) {
        const int kw = (c == 2) ? 64 : 128;
        __syncthreads();
        if (c < 2) {            // embedding region: transposed staging (coalesced gather)
            for (int e = tid; e < 128 * 64; e += 128) {
                int b = e >> 7, kl = e & 127;
                xs[kl * 66 + b] = emb_dec[(size_t)g_idx[b] * EMB + koff[c] + kl];
            }
        } else if (c == 2) {    // rate + zero pad
            for (int e = tid; e < 64 * 64; e += 128) {
                int kl = e >> 6, b = e & 63;
                xs[kl * 66 + b] = (kl == 0) ? g_rate[b] : 0.f;
            }
        } else {                // hidden region
            int h0 = koff[c] - 320;
            for (int e = tid; e < 128 * 32; e += 128) {
                int k = e >> 5, bp = e & 31;
                *reinterpret_cast<float2*>(&xs[k * 66 + 2 * bp]) =
                    *reinterpret_cast<const float2*>(&hin[(h0 + k) * 64 + 2 * bp]);
            }
        }
        __syncthreads();
        const float* wp = ws4 + (size_t)(jl * KF + koff[c]) * 4;
        if (c < 3) gru_inner(xs, wp, kw, lane, aR, aZ, aNi);
        else       gru_inner(xs, wp, kw, lane, aR, aZ, aNh);
    }

    int j = j0 + jl;
    float bir = b_ih[j] + b_hh[j], biz = b_ih[j + 512] + b_hh[j + 512];
    float bin = b_ih[j + 1024], bhn = b_hh[j + 1024];
    #pragma unroll
    for (int u = 0; u < 2; u++) {
        int b = 2 * lane + u;
        float r = sigf((u ? aR.y : aR.x) + bir);
        float z = sigf((u ? aZ.y : aZ.x) + biz);
        float n = tanhf(((u ? aNi.y : aNi.x) + bin) + r * ((u ? aNh.y : aNh.x) + bhn));
        float ho = hin[j * 64 + b];
        hout[j * 64 + b] = (1.f - z) * n + z * ho;
    }
}

// ---------------- logits GEMM + Yh, ticket-scheduled ----------------
__global__ void logits_kernel(const float* __restrict__ hnew,
                              const float* __restrict__ W_eid, const float* __restrict__ b_eid,
                              const float* __restrict__ W_r1, int step) {
    extern __shared__ float sm[];
    float* xs = sm;              // [256 k][66]
    float* ws = sm + 256 * 66;   // [64 n][65]
    __shared__ unsigned sh_t;
    const int tid = threadIdx.x;
    const int bpg = tid & 7, cg = tid >> 3;

    for (;;) {
        __syncthreads();
        if (tid == 0) sh_t = atomicAdd(&g_tk[step], 1u);
        __syncthreads();
        unsigned t = sh_t;
        if (t >= NTILES) break;
        const bool isY = (t >= 469);
        const int n0 = isY ? (int)(t - 469) * 64 : (int)t * 64;

        float2 acc[4][4];
        #pragma unroll
        for (int i = 0; i < 4; i++)
            #pragma unroll
            for (int c = 0; c < 4; c++) acc[i][c] = make_float2(0.f, 0.f);

        for (int kt = 0; kt < HID; kt += 256) {
            __syncthreads();
            for (int e = tid; e < 256 * 32; e += 128) {
                int k = e >> 5, bp = e & 31;
                *reinterpret_cast<float2*>(&xs[k * 66 + 2 * bp]) =
                    *reinterpret_cast<const float2*>(&hnew[(kt + k) * 64 + 2 * bp]);
            }
            for (int sub = 0; sub < 4; sub++) {
                __syncthreads();
                int ks = kt + sub * 64;
                for (int e = tid; e < 4096; e += 128) {
                    int nl = e >> 6, k = e & 63; int n = n0 + nl;
                    ws[nl * 65 + k] = isY ? W_r1[(size_t)n * 768 + 256 + ks + k]
                                          : ((n < EID) ? W_eid[(size_t)n * HID + ks + k] : 0.f);
                }
                __syncthreads();
                mm64_4x4(xs + sub * 64 * 66, ws, bpg, cg, acc);
            }
        }

        #pragma unroll
        for (int c = 0; c < 4; c++) {
            int n = n0 + cg * 4 + c;
            if (isY) {
                #pragma unroll
                for (int i = 0; i < 4; i++) {
                    int p = bpg + 8 * i;
                    g_Yh[(2 * p) * HID + n]     = acc[i][c].x;
                    g_Yh[(2 * p + 1) * HID + n] = acc[i][c].y;
                }
            } else if (n < EID) {
                float bv = b_eid[n];
                #pragma unroll
                for (int i = 0; i < 4; i++) {
                    int p = bpg + 8 * i;
                    g_logits[(size_t)(2 * p) * EID + n]     = acc[i][c].x + bv;
                    g_logits[(size_t)(2 * p + 1) * EID + n] = acc[i][c].y + bv;
                }
            }
        }
    }
}

// ---------------- softmax + argmax + rate head + output write ----------------
__global__ void softmax_head(float* __restrict__ out, int s,
                             const float* __restrict__ b_r1, const float* __restrict__ W_r2,
                             const float* __restrict__ b_r2) {
    __shared__ float rm[1024], rs[1024];
    __shared__ int   ri[1024];
    const int b = blockIdx.x, tid = threadIdx.x;
    const float* L = g_logits + (size_t)b * EID;

    float m = -3.4e38f, sum = 0.f; int ix = 0x7fffffff;
    for (int n = tid; n < EID; n += 1024) {
        float v = L[n];
        if (v > m) { sum = sum * expf(m - v) + 1.f; m = v; ix = n; }
        else       sum += expf(v - m);
    }
    rm[tid] = m; rs[tid] = sum; ri[tid] = ix;
    __syncthreads();
    for (int st = 512; st; st >>= 1) {
        if (tid < st) {
            float m1 = rm[tid], m2 = rm[tid + st], s1 = rs[tid], s2 = rs[tid + st];
            int i1 = ri[tid], i2 = ri[tid + st];
            float M = fmaxf(m1, m2);
            rs[tid] = s1 * expf(m1 - M) + s2 * expf(m2 - M);
            rm[tid] = M;
            ri[tid] = (m2 > m1) ? i2 : ((m1 > m2) ? i1 : min(i1, i2));
        }
        __syncthreads();
    }
    float lse = rm[0] + logf(rs[0]);
    int amax = ri[0];
    if (tid == 0) g_idx[b] = amax;
    __syncthreads();

    // rate head: r1 = mtProj[amax] + Yh[b] + b_r1; sigmoid(relu(r1)·W_r2 + b_r2)
    if (tid < 512) {
        float v = g_mtProj[(size_t)amax * HID + tid] + g_Yh[b * HID + tid] + b_r1[tid];
        rm[tid] = fmaxf(v, 0.f) * W_r2[tid];
    }
    __syncthreads();
    for (int st = 256; st; st >>= 1) { if (tid < st) rm[tid] += rm[tid + st]; __syncthreads(); }
    if (tid == 0) {
        float pr = sigf(rm[0] + b_r2[0]);
        out[(size_t)TRG_T * B * EID + (size_t)(s + 1) * B + b] = pr;
        g_rate[b] = pr;
    }

    float* O = out + ((size_t)(s + 1) * B + b) * EID;
    for (int n = tid; n < EID; n += 1024) O[n] = L[n] - lse;
}

// ---------------- host launcher ----------------
extern "C" void kernel_launch(void* const* d_in, const int* in_sizes, int n_in,
                              void* d_out, int out_size)
{
    const float* src      = (const float*)d_in[0];
    const int*   src_len  = (const int*)  d_in[1];
    const int*   trg_eid  = (const int*)  d_in[2];
    const float* trg_rate = (const float*)d_in[3];
    const float* W_ih_enc = (const float*)d_in[4];
    const float* W_hh_enc = (const float*)d_in[5];
    const float* b_ih_enc = (const float*)d_in[6];
    const float* b_hh_enc = (const float*)d_in[7];
    const float* emb_dec  = (const float*)d_in[8];
    const float* W_ih_dec = (const float*)d_in[9];
    const float* W_hh_dec = (const float*)d_in[10];
    const float* b_ih_dec = (const float*)d_in[11];
    const float* b_hh_dec = (const float*)d_in[12];
    const float* emb_mt   = (const float*)d_in[13];
    const float* W_eid    = (const float*)d_in[14];
    const float* b_eid    = (const float*)d_in[15];
    const float* W_r1     = (const float*)d_in[16];
    const float* b_r1     = (const float*)d_in[17];
    const float* W_r2     = (const float*)d_in[18];
    const float* b_r2     = (const float*)d_in[19];
    float* out = (float*)d_out;
    float* out_rate = out + (size_t)TRG_T * B * EID;

    const int SM_ENC = (4 * 512 * 4 + 128 * 66) * 4;   // 66560
    const int SM_DEC = (4 * KF * 4 + 128 * 66) * 4;    // 86912
    const int SM_LOG = (256 * 66 + 64 * 65) * 4;       // 84224
    cudaFuncSetAttribute(enc_step_kernel, cudaFuncAttributeMaxDynamicSharedMemorySize, SM_ENC);
    cudaFuncSetAttribute(dec_gru_kernel,  cudaFuncAttributeMaxDynamicSharedMemorySize, SM_DEC);
    cudaFuncSetAttribute(logits_kernel,   cudaFuncAttributeMaxDynamicSharedMemorySize, SM_LOG);

    float* hT;
    cudaGetSymbolAddress((void**)&hT, g_hT);
    float* hbuf[2] = { hT, hT + HID * B };

    // zero output row 0
    cudaMemsetAsync(out, 0, (size_t)B * EID * sizeof(float), 0);
    cudaMemsetAsync(out_rate, 0, B * sizeof(float), 0);

    // one-time prep
    init_state<<<128, 256>>>(trg_eid, trg_rate);
    build_wdec<<<(G3 * KF + 255) / 256, 256>>>(W_ih_dec, W_hh_dec);
    transpose_emb<<<dim3(938, 8), 256>>>(emb_mt);
    mtproj_kernel<<<469 * 8, 128>>>(W_r1);
    enc_gi<<<dim3(6, SRC_T * B), 256>>>(src, W_ih_enc, b_ih_enc);

    // encoder: 1 node per step
    float* giE;
    cudaGetSymbolAddress((void**)&giE, g_giEnc);
    for (int t = 0; t < SRC_T; t++) {
        enc_step_kernel<<<128, 128, SM_ENC>>>(hbuf[t & 1], hbuf[(t + 1) & 1],
                                              W_hh_enc, b_hh_enc,
                                              giE + (size_t)t * B * G3, src_len, t);
    }

    // decoder: 3 nodes per step
    for (int s = 0; s < TRG_T - 1; s++) {
        const int pi = s & 1, po = (s + 1) & 1;
        dec_gru_kernel<<<128, 128, SM_DEC>>>(hbuf[pi], hbuf[po], emb_dec, b_ih_dec, b_hh_dec);
        logits_kernel<<<296, 128, SM_LOG>>>(hbuf[po], W_eid, b_eid, W_r1, s);
        softmax_head<<<64, 1024>>>(out, s, b_r1, W_r2, b_r2);
    }
}